// round 16
// baseline (speedup 1.0000x reference)
#include <cuda_runtime.h>
#include <cuda_fp16.h>
#include <cstdint>

#define BATCH  64
#define HID    1024
#define VOCAB  4096
#define SEQ    256
#define NBLK   64
#define NTHR   512
#define CH     256                 // A-chunk width (K cols), fp16
#define NCH    (HID / CH)          // 4 chunks
#define CHP    264                 // padded row stride (halves)
#define NSTG   3                   // cp.async pipeline stages
#define CSTR   34                  // sRed row stride: 16 cols * 2 kq + 2 pad

// ---------------------------------------------------------------------------
// Global scratch
// ---------------------------------------------------------------------------
__device__ float  g_H[(SEQ + 1) * BATCH * HID];   // fp32 history (output GEMM)
__device__ __half g_Hh[BATCH * HID];              // fp16 current H (GEMM operand)
__device__ __half g_Ph[BATCH * HID];              // fp16 P = r*H (GEMM operand)
__device__ unsigned g_bar_count = 0;
__device__ unsigned g_bar_gen   = 0;

// ---------------------------------------------------------------------------
// helpers
// ---------------------------------------------------------------------------
__device__ __forceinline__ float tf32r(float x) {
    unsigned u;
    asm("cvt.rna.tf32.f32 %0, %1;" : "=r"(u) : "f"(x));
    return __uint_as_float(u);
}

// tf32 m16n8k8 (output GEMM only)
__device__ __forceinline__ void mma8(float (&c)[4], const float (&a)[4], float b0, float b1) {
    unsigned a0 = __float_as_uint(a[0]), a1 = __float_as_uint(a[1]);
    unsigned a2 = __float_as_uint(a[2]), a3 = __float_as_uint(a[3]);
    unsigned B0 = __float_as_uint(b0),  B1 = __float_as_uint(b1);
    asm volatile(
        "mma.sync.aligned.m16n8k8.row.col.f32.tf32.tf32.f32 "
        "{%0,%1,%2,%3}, {%4,%5,%6,%7}, {%8,%9}, {%0,%1,%2,%3};\n"
        : "+f"(c[0]), "+f"(c[1]), "+f"(c[2]), "+f"(c[3])
        : "r"(a0), "r"(a1), "r"(a2), "r"(a3), "r"(B0), "r"(B1));
}

// fp16 m16n8k16, fp32 accumulate (recurrence GEMMs)
__device__ __forceinline__ void mma16(float (&c)[4],
                                      unsigned a0, unsigned a1, unsigned a2, unsigned a3,
                                      unsigned b0, unsigned b1) {
    asm volatile(
        "mma.sync.aligned.m16n8k16.row.col.f32.f16.f16.f32 "
        "{%0,%1,%2,%3}, {%4,%5,%6,%7}, {%8,%9}, {%0,%1,%2,%3};\n"
        : "+f"(c[0]), "+f"(c[1]), "+f"(c[2]), "+f"(c[3])
        : "r"(a0), "r"(a1), "r"(a2), "r"(a3), "r"(b0), "r"(b1));
}

__device__ __forceinline__ float sigmoidf_(float x) { return 1.f / (1.f + __expf(-x)); }

__device__ __forceinline__ unsigned packh2(float lo, float hi) {
    __half2 h = __floats2half2_rn(lo, hi);
    return *reinterpret_cast<unsigned*>(&h);
}

__device__ __forceinline__ void cpasync16(uint32_t daddr, const void* gptr) {
    asm volatile("cp.async.cg.shared.global [%0], [%1], 16;\n"
                 :: "r"(daddr), "l"(gptr) : "memory");
}
__device__ __forceinline__ void cpasync_commit() {
    asm volatile("cp.async.commit_group;\n" ::: "memory");
}
template<int N>
__device__ __forceinline__ void cpasync_wait() {
    asm volatile("cp.async.wait_group %0;\n" :: "n"(N) : "memory");
}

// Light release/acquire grid barrier (thread 0 only touches global).
__device__ __forceinline__ void gridbar() {
    __syncthreads();
    if (threadIdx.x == 0) {
        unsigned gen;
        asm volatile("ld.relaxed.gpu.global.u32 %0, [%1];"
                     : "=r"(gen) : "l"(&g_bar_gen) : "memory");
        unsigned old;
        asm volatile("atom.acq_rel.gpu.global.add.u32 %0, [%1], 1;"
                     : "=r"(old) : "l"(&g_bar_count) : "memory");
        if (old == NBLK - 1) {
            asm volatile("st.relaxed.gpu.global.u32 [%0], %1;"
                         :: "l"(&g_bar_count), "r"(0u) : "memory");
            asm volatile("st.release.gpu.global.u32 [%0], %1;"
                         :: "l"(&g_bar_gen), "r"(gen + 1) : "memory");
        } else {
            unsigned cur;
            do {
                asm volatile("ld.acquire.gpu.global.u32 %0, [%1];"
                             : "=r"(cur) : "l"(&g_bar_gen) : "memory");
            } while (cur == gen);
        }
    }
    __syncthreads();
}

// ---------------------------------------------------------------------------
// Persistent recurrence: 64 blocks x 512 threads; block b owns cols
// [16b, 16b+16) of ALL THREE gates. fp16 m16n8k16 GEMMs, fp32 state.
//   Warps: wid = mt*4 + nt*2 + kq  (mt: 16-row tile, nt: 8-col half, kq: K-half)
//   Single-sync 3-stage cp.async ring over NCH=4 chunks of 256 K.
// ---------------------------------------------------------------------------
__global__ void __launch_bounds__(NTHR, 1)
gru_persist(const int* __restrict__ X,
            const float* __restrict__ Wz, const float* __restrict__ bz,
            const float* __restrict__ Wr, const float* __restrict__ br,
            const float* __restrict__ Wh, const float* __restrict__ bh)
{
    extern __shared__ unsigned char smraw[];
    uint32_t* sWa32 = reinterpret_cast<uint32_t*>(smraw);        // 16384 u32 (64KB)
    uint32_t* sWh32 = sWa32 + 16384;                             //  8192 u32 (32KB)
    __half*   sAh   = reinterpret_cast<__half*>(sWh32 + 8192);   // 3*64*CHP halves (~99KB)
    float*    sRed  = reinterpret_cast<float*>(sAh + NSTG * 64 * CHP);  // 2*64*CSTR f (17KB)
    float*    sZ    = sRed + 2 * 64 * CSTR;                      // 1024 f
    float*    sHc   = sZ + 1024;                                 // 1024 f (own-col H, fp32)

    const int tid  = threadIdx.x;
    const int bid  = blockIdx.x;
    const int lane = tid & 31;
    const int wid  = tid >> 5;
    const int mt   = wid >> 2;
    const int nt   = (wid >> 1) & 1;
    const int kq   = wid & 1;
    const int gid  = lane >> 2;
    const int tg   = lane & 3;
    const int n0   = bid * 16;

    uint32_t sbase = (uint32_t)__cvta_generic_to_shared(sAh);

    // ---- pack weights once (fp16 b-fragments, RNE) ----
    // sWa32[e]: e = (k16*32 + lane)*8 + nt*4 + gate*2 + reg ; gate: 0=z,1=r
    for (int e = tid; e < 16384; e += NTHR) {
        int reg = e & 1, gate = (e >> 1) & 1, ntp = (e >> 2) & 1;
        int ln  = (e >> 3) & 31, k16 = e >> 8;
        int kb  = k16 * 16 + reg * 8 + 2 * (ln & 3);
        int col = n0 + ntp * 8 + (ln >> 2);
        const float* W = gate ? Wr : Wz;
        sWa32[e] = packh2(W[(size_t)(VOCAB + kb) * HID + col],
                          W[(size_t)(VOCAB + kb + 1) * HID + col]);
    }
    // sWh32[e]: e = (k16*32 + lane)*4 + nt*2 + reg
    for (int e = tid; e < 8192; e += NTHR) {
        int reg = e & 1, ntp = (e >> 1) & 1;
        int ln  = (e >> 2) & 31, k16 = e >> 7;
        int kb  = k16 * 16 + reg * 8 + 2 * (ln & 3);
        int col = n0 + ntp * 8 + (ln >> 2);
        sWh32[e] = packh2(Wh[(size_t)(VOCAB + kb) * HID + col],
                          Wh[(size_t)(VOCAB + kb + 1) * HID + col]);
    }

    // bias preload: 2 epilogue elements per thread
    float bzv[2], brv[2], bhv[2];
    int eidx[2], erowv[2], env[2];
#pragma unroll
    for (int s = 0; s < 2; ++s) {
        int i = tid + s * NTHR;
        eidx[s] = i; erowv[s] = i >> 4; env[s] = n0 + (i & 15);
        bzv[s] = bz[env[s]]; brv[s] = br[env[s]]; bhv[s] = bh[env[s]];
    }

    // init: H0 = 0 (fp16 operand buffer + own-col fp32 state)
    reinterpret_cast<unsigned*>(g_Hh)[bid * NTHR + tid] = 0u;   // 64*512*2 halves = 64K
    sHc[tid] = 0.f; sHc[tid + NTHR] = 0.f;
    gridbar();

    for (int t = 0; t < SEQ; ++t) {
        float* Hn = g_H + (size_t)(t + 1) * (BATCH * HID);

        // prefetch gather operands for both epilogues
        float wzv[2], wrv[2], whv[2];
#pragma unroll
        for (int s = 0; s < 2; ++s) {
            const int x = __ldg(X + erowv[s] * SEQ + t);
            const size_t wix = (size_t)x * HID + env[s];
            wzv[s] = __ldg(Wz + wix);
            wrv[s] = __ldg(Wr + wix);
            whv[s] = __ldg(Wh + wix);
        }

        // ================= Phase A: z and r =================
        {
            float az[4] = {0,0,0,0}, ar[4] = {0,0,0,0};

            // prologue: chunks 0..2 -> stages 0..2
#pragma unroll
            for (int c = 0; c < NSTG; ++c) {
#pragma unroll
                for (int j = 0; j < 4; ++j) {
                    int seg = j * NTHR + tid;
                    int row = seg >> 5, s = seg & 31;
                    uint32_t d = sbase + (c * (64 * CHP) + row * CHP + s * 8) * 2;
                    cpasync16(d, g_Hh + (size_t)row * HID + c * CH + s * 8);
                }
                cpasync_commit();
            }

#pragma unroll
            for (int it = 0; it < NCH; ++it) {
                if (it == 0)           cpasync_wait<NSTG - 1>();
                else if (it + 1 < NCH) cpasync_wait<1>();
                else                   cpasync_wait<0>();
                __syncthreads();

                if (it >= 1 && it + 2 < NCH) {
                    int c = it + 2;
#pragma unroll
                    for (int j = 0; j < 4; ++j) {
                        int seg = j * NTHR + tid;
                        int row = seg >> 5, s = seg & 31;
                        uint32_t d = sbase + ((c % NSTG) * (64 * CHP) + row * CHP + s * 8) * 2;
                        cpasync16(d, g_Hh + (size_t)row * HID + c * CH + s * 8);
                    }
                    cpasync_commit();
                }

                const __half* stg = sAh + (it % NSTG) * (64 * CHP);
                const int row0 = mt * 16 + gid;
#pragma unroll
                for (int i = 0; i < 8; ++i) {
                    int k16l = kq * 8 + i;
                    int kk   = k16l * 16;
                    unsigned u0 = *reinterpret_cast<const unsigned*>(stg + row0 * CHP + kk + 2 * tg);
                    unsigned u1 = *reinterpret_cast<const unsigned*>(stg + (row0 + 8) * CHP + kk + 2 * tg);
                    unsigned u2 = *reinterpret_cast<const unsigned*>(stg + row0 * CHP + kk + 8 + 2 * tg);
                    unsigned u3 = *reinterpret_cast<const unsigned*>(stg + (row0 + 8) * CHP + kk + 8 + 2 * tg);
                    int k16g = it * 16 + k16l;
                    uint4 w = *reinterpret_cast<const uint4*>(
                        sWa32 + (size_t)(k16g * 32 + lane) * 8 + nt * 4);
                    mma16(az, u0, u1, u2, u3, w.x, w.y);
                    mma16(ar, u0, u1, u2, u3, w.z, w.w);
                }
            }

            // partials -> sRed[gate][row][col*2 + kq]
#pragma unroll
            for (int j = 0; j < 4; ++j) {
                int prow = mt * 16 + gid + (j >> 1) * 8;
                int pcol = nt * 8 + tg * 2 + (j & 1);
                sRed[prow * CSTR + pcol * 2 + kq]              = az[j];
                sRed[64 * CSTR + prow * CSTR + pcol * 2 + kq]  = ar[j];
            }
            __syncthreads();

            // wide epilogue: 2 (row,col) per thread
#pragma unroll
            for (int s = 0; s < 2; ++s) {
                int erow = erowv[s], ecol = eidx[s] & 15, en = env[s];
                float2 zp = *reinterpret_cast<const float2*>(sRed + erow * CSTR + ecol * 2);
                float2 rp = *reinterpret_cast<const float2*>(sRed + 64 * CSTR + erow * CSTR + ecol * 2);
                float zv = sigmoidf_(zp.x + zp.y + wzv[s] + bzv[s]);
                float rv = sigmoidf_(rp.x + rp.y + wrv[s] + brv[s]);
                sZ[eidx[s]] = zv;
                g_Ph[erow * HID + en] = __float2half_rn(rv * sHc[eidx[s]]);
            }
        }
        gridbar();

        // ================= Phase B: h gate + H update =================
        {
            float ah[4] = {0,0,0,0};

#pragma unroll
            for (int c = 0; c < NSTG; ++c) {
#pragma unroll
                for (int j = 0; j < 4; ++j) {
                    int seg = j * NTHR + tid;
                    int row = seg >> 5, s = seg & 31;
                    uint32_t d = sbase + (c * (64 * CHP) + row * CHP + s * 8) * 2;
                    cpasync16(d, g_Ph + (size_t)row * HID + c * CH + s * 8);
                }
                cpasync_commit();
            }

#pragma unroll
            for (int it = 0; it < NCH; ++it) {
                if (it == 0)           cpasync_wait<NSTG - 1>();
                else if (it + 1 < NCH) cpasync_wait<1>();
                else                   cpasync_wait<0>();
                __syncthreads();

                if (it >= 1 && it + 2 < NCH) {
                    int c = it + 2;
#pragma unroll
                    for (int j = 0; j < 4; ++j) {
                        int seg = j * NTHR + tid;
                        int row = seg >> 5, s = seg & 31;
                        uint32_t d = sbase + ((c % NSTG) * (64 * CHP) + row * CHP + s * 8) * 2;
                        cpasync16(d, g_Ph + (size_t)row * HID + c * CH + s * 8);
                    }
                    cpasync_commit();
                }

                const __half* stg = sAh + (it % NSTG) * (64 * CHP);
                const int row0 = mt * 16 + gid;
#pragma unroll
                for (int i = 0; i < 8; ++i) {
                    int k16l = kq * 8 + i;
                    int kk   = k16l * 16;
                    unsigned u0 = *reinterpret_cast<const unsigned*>(stg + row0 * CHP + kk + 2 * tg);
                    unsigned u1 = *reinterpret_cast<const unsigned*>(stg + (row0 + 8) * CHP + kk + 2 * tg);
                    unsigned u2 = *reinterpret_cast<const unsigned*>(stg + row0 * CHP + kk + 8 + 2 * tg);
                    unsigned u3 = *reinterpret_cast<const unsigned*>(stg + (row0 + 8) * CHP + kk + 8 + 2 * tg);
                    int k16g = it * 16 + k16l;
                    uint2 w = *reinterpret_cast<const uint2*>(
                        sWh32 + (size_t)(k16g * 32 + lane) * 4 + nt * 2);
                    mma16(ah, u0, u1, u2, u3, w.x, w.y);
                }
            }

#pragma unroll
            for (int j = 0; j < 4; ++j) {
                int prow = mt * 16 + gid + (j >> 1) * 8;
                int pcol = nt * 8 + tg * 2 + (j & 1);
                sRed[prow * CSTR + pcol * 2 + kq] = ah[j];
            }
            __syncthreads();

#pragma unroll
            for (int s = 0; s < 2; ++s) {
                int erow = erowv[s], ecol = eidx[s] & 15, en = env[s];
                float2 hp = *reinterpret_cast<const float2*>(sRed + erow * CSTR + ecol * 2);
                float hv = tanhf(hp.x + hp.y + whv[s] + bhv[s]);
                float zv = sZ[eidx[s]];
                float hcold = sHc[eidx[s]];
                float hnew = zv * hv + (1.f - zv) * hcold;
                sHc[eidx[s]] = hnew;
                Hn[erow * HID + en] = hnew;                       // fp32 history
                g_Hh[erow * HID + en] = __float2half_rn(hnew);    // fp16 operand
            }
        }
        gridbar();
    }
}

// ---------------------------------------------------------------------------
// Output GEMM: Y = H_all[16384 x 1024] @ Wo[1024 x 4096] + bo
//   128x128 block tile, 512 threads (known-good R13 version, tf32).
// ---------------------------------------------------------------------------
__global__ void __launch_bounds__(512)
gru_out3(const float* __restrict__ Wo, const float* __restrict__ bo,
         float* __restrict__ out)
{
    __shared__ float As[128 * 36];
    __shared__ float Bs[32 * 136];

    const int n0 = blockIdx.x * 128;
    const int m0 = blockIdx.y * 128;
    const float* A = g_H + (size_t)(BATCH * HID) + (size_t)m0 * HID;

    const int tid = threadIdx.x, lane = tid & 31, w = tid >> 5;
    const int wm = w >> 2, wn = w & 3, gid = lane >> 2, tg = lane & 3;

    float acc[2][4][4];
#pragma unroll
    for (int mi = 0; mi < 2; ++mi)
#pragma unroll
        for (int ni = 0; ni < 4; ++ni)
#pragma unroll
            for (int e = 0; e < 4; ++e) acc[mi][ni][e] = 0.f;

    float4 ra[2]; float4 rb[2];
#pragma unroll
    for (int j = 0; j < 2; ++j) {
        int i = tid + j * 512, row = i >> 3, kq8 = i & 7;
        ra[j] = *reinterpret_cast<const float4*>(A + (size_t)row * HID + kq8 * 4);
    }
#pragma unroll
    for (int j = 0; j < 2; ++j) {
        int i = tid + j * 512, row = i >> 5, nq = i & 31;
        rb[j] = *reinterpret_cast<const float4*>(Wo + (size_t)row * VOCAB + n0 + nq * 4);
    }

    for (int kk = 0; kk < HID; kk += 32) {
#pragma unroll
        for (int j = 0; j < 2; ++j) {
            int i = tid + j * 512, row = i >> 3, kq8 = i & 7;
            float4 v; v.x = tf32r(ra[j].x); v.y = tf32r(ra[j].y);
            v.z = tf32r(ra[j].z); v.w = tf32r(ra[j].w);
            *reinterpret_cast<float4*>(As + row * 36 + kq8 * 4) = v;
        }
#pragma unroll
        for (int j = 0; j < 2; ++j) {
            int i = tid + j * 512, row = i >> 5, nq = i & 31;
            float4 v; v.x = tf32r(rb[j].x); v.y = tf32r(rb[j].y);
            v.z = tf32r(rb[j].z); v.w = tf32r(rb[j].w);
            *reinterpret_cast<float4*>(Bs + row * 136 + nq * 4) = v;
        }
        __syncthreads();
        if (kk + 32 < HID) {
#pragma unroll
            for (int j = 0; j < 2; ++j) {
                int i = tid + j * 512, row = i >> 3, kq8 = i & 7;
                ra[j] = *reinterpret_cast<const float4*>(A + (size_t)row * HID + kk + 32 + kq8 * 4);
            }
#pragma unroll
            for (int j = 0; j < 2; ++j) {
                int i = tid + j * 512, row = i >> 5, nq = i & 31;
                rb[j] = *reinterpret_cast<const float4*>(
                    Wo + (size_t)(kk + 32 + row) * VOCAB + n0 + nq * 4);
            }
        }
#pragma unroll
        for (int k8 = 0; k8 < 4; ++k8) {
            int kb = k8 * 8;
            float a[2][4];
#pragma unroll
            for (int mi = 0; mi < 2; ++mi) {
                int rb0 = wm * 32 + mi * 16;
                a[mi][0] = As[(rb0 + gid) * 36 + kb + tg];
                a[mi][1] = As[(rb0 + 8 + gid) * 36 + kb + tg];
                a[mi][2] = As[(rb0 + gid) * 36 + kb + 4 + tg];
                a[mi][3] = As[(rb0 + 8 + gid) * 36 + kb + 4 + tg];
            }
#pragma unroll
            for (int ni = 0; ni < 4; ++ni) {
                int col = wn * 32 + ni * 8 + gid;
                float b0 = Bs[(kb + tg) * 136 + col];
                float b1 = Bs[(kb + 4 + tg) * 136 + col];
#pragma unroll
                for (int mi = 0; mi < 2; ++mi) mma8(acc[mi][ni], a[mi], b0, b1);
            }
        }
        __syncthreads();
    }

#pragma unroll
    for (int mi = 0; mi < 2; ++mi)
#pragma unroll
        for (int half = 0; half < 2; ++half) {
            int row = m0 + wm * 32 + mi * 16 + half * 8 + gid;
#pragma unroll
            for (int ni = 0; ni < 4; ++ni)
#pragma unroll
                for (int e = 0; e < 2; ++e) {
                    int n = n0 + wn * 32 + ni * 8 + tg * 2 + e;
                    out[(size_t)row * VOCAB + n] = acc[mi][ni][half * 2 + e] + bo[n];
                }
        }
}

__global__ void gru_copy_hfinal(float* __restrict__ dst) {
    int i = blockIdx.x * blockDim.x + threadIdx.x;
    if (i < BATCH * HID) dst[i] = g_H[(size_t)SEQ * (BATCH * HID) + i];
}

// ---------------------------------------------------------------------------
extern "C" void kernel_launch(void* const* d_in, const int* in_sizes, int n_in,
                              void* d_out, int out_size)
{
    const int*   X  = (const int*)  d_in[0];
    const float* Wz = (const float*)d_in[1];
    const float* bz = (const float*)d_in[2];
    const float* Wr = (const float*)d_in[3];
    const float* br = (const float*)d_in[4];
    const float* Wh = (const float*)d_in[5];
    const float* bh = (const float*)d_in[6];
    const float* Wo = (const float*)d_in[7];
    const float* bo = (const float*)d_in[8];
    float* out = (float*)d_out;

    const int smemBytes = 16384 * 4           // sWa32 (64KB)
                        + 8192 * 4            // sWh32 (32KB)
                        + NSTG * 64 * CHP * 2 // fp16 A ring (~99KB)
                        + 2 * 64 * CSTR * 4   // sRed (17KB)
                        + 1024 * 4            // sZ
                        + 1024 * 4;           // sHc  => 225280 B
    cudaFuncSetAttribute(gru_persist, cudaFuncAttributeMaxDynamicSharedMemorySize, smemBytes);

    gru_persist<<<NBLK, NTHR, smemBytes>>>(X, Wz, bz, Wr, br, Wh, bh);

    gru_out3<<<dim3(VOCAB / 128, (SEQ * BATCH) / 128), 512>>>(Wo, bo, out);

    const long long ybytes = (long long)SEQ * BATCH * VOCAB;
    if ((long long)out_size >= ybytes + (long long)BATCH * HID) {
        gru_copy_hfinal<<<64, 1024>>>(out + ybytes);
    }
    (void)in_sizes; (void)n_in;
}

// round 17
// speedup vs baseline: 1.0446x; 1.0446x over previous
#include <cuda_runtime.h>
#include <cuda_fp16.h>
#include <cstdint>

#define BATCH  64
#define HID    1024
#define VOCAB  4096
#define SEQ    256
#define NBLK   128
#define NTHR   512
#define CH     256                 // A-chunk width (K cols), fp16
#define NCH    (HID / CH)          // 4 chunks
#define CHP    264                 // padded row stride (halves)
#define NSTG   3                   // cp.async pipeline stages
#define RSTR   36                  // sRed row stride (8 cols * 4 kq + 4 pad)
#define NGRP   8                   // barrier tree: 8 groups of 16 blocks
#define GSTR   64                  // group-counter stride (u32) = 256B

// ---------------------------------------------------------------------------
// Global scratch
// ---------------------------------------------------------------------------
__device__ float  g_H[(SEQ + 1) * BATCH * HID];   // fp32 history (output GEMM)
__device__ __half g_Hh[BATCH * HID];              // fp16 current H (GEMM operand)
__device__ __half g_Ph[BATCH * HID];              // fp16 P = r*H (GEMM operand)
__device__ unsigned g_grp[NGRP * GSTR];           // tree-barrier group counters
__device__ unsigned g_root = 0;
__device__ unsigned g_gen  = 0;

// ---------------------------------------------------------------------------
// helpers
// ---------------------------------------------------------------------------
__device__ __forceinline__ float tf32r(float x) {
    unsigned u;
    asm("cvt.rna.tf32.f32 %0, %1;" : "=r"(u) : "f"(x));
    return __uint_as_float(u);
}

// tf32 m16n8k8 (output GEMM only)
__device__ __forceinline__ void mma8(float (&c)[4], const float (&a)[4], float b0, float b1) {
    unsigned a0 = __float_as_uint(a[0]), a1 = __float_as_uint(a[1]);
    unsigned a2 = __float_as_uint(a[2]), a3 = __float_as_uint(a[3]);
    unsigned B0 = __float_as_uint(b0),  B1 = __float_as_uint(b1);
    asm volatile(
        "mma.sync.aligned.m16n8k8.row.col.f32.tf32.tf32.f32 "
        "{%0,%1,%2,%3}, {%4,%5,%6,%7}, {%8,%9}, {%0,%1,%2,%3};\n"
        : "+f"(c[0]), "+f"(c[1]), "+f"(c[2]), "+f"(c[3])
        : "r"(a0), "r"(a1), "r"(a2), "r"(a3), "r"(B0), "r"(B1));
}

// fp16 m16n8k16, fp32 accumulate (recurrence GEMMs)
__device__ __forceinline__ void mma16(float (&c)[4],
                                      unsigned a0, unsigned a1, unsigned a2, unsigned a3,
                                      unsigned b0, unsigned b1) {
    asm volatile(
        "mma.sync.aligned.m16n8k16.row.col.f32.f16.f16.f32 "
        "{%0,%1,%2,%3}, {%4,%5,%6,%7}, {%8,%9}, {%0,%1,%2,%3};\n"
        : "+f"(c[0]), "+f"(c[1]), "+f"(c[2]), "+f"(c[3])
        : "r"(a0), "r"(a1), "r"(a2), "r"(a3), "r"(b0), "r"(b1));
}

__device__ __forceinline__ float sigmoidf_(float x) { return 1.f / (1.f + __expf(-x)); }

__device__ __forceinline__ unsigned packh2(float lo, float hi) {
    __half2 h = __floats2half2_rn(lo, hi);
    return *reinterpret_cast<unsigned*>(&h);
}

__device__ __forceinline__ void cpasync16(uint32_t daddr, const void* gptr) {
    asm volatile("cp.async.cg.shared.global [%0], [%1], 16;\n"
                 :: "r"(daddr), "l"(gptr) : "memory");
}
__device__ __forceinline__ void cpasync_commit() {
    asm volatile("cp.async.commit_group;\n" ::: "memory");
}
template<int N>
__device__ __forceinline__ void cpasync_wait() {
    asm volatile("cp.async.wait_group %0;\n" :: "n"(N) : "memory");
}

// Two-level tree grid barrier: 8 group counters (16 arrivals each, 256B apart)
// feed an 8-way root. acq_rel atomic chain keeps release/acquire transitivity:
// block writes -> syncthreads -> group atom (release) -> root atom -> gen
// st.release -> spinners ld.acquire.
__device__ __forceinline__ void gridbar(int grp) {
    __syncthreads();
    if (threadIdx.x == 0) {
        unsigned gen;
        asm volatile("ld.relaxed.gpu.global.u32 %0, [%1];"
                     : "=r"(gen) : "l"(&g_gen) : "memory");
        unsigned go;
        asm volatile("atom.acq_rel.gpu.global.add.u32 %0, [%1], 1;"
                     : "=r"(go) : "l"(&g_grp[grp * GSTR]) : "memory");
        if (go == (NBLK / NGRP) - 1) {
            // last in group: reset group counter (safe: nobody re-arrives
            // until gen flips), then arrive at root
            asm volatile("st.relaxed.gpu.global.u32 [%0], %1;"
                         :: "l"(&g_grp[grp * GSTR]), "r"(0u) : "memory");
            unsigned ro;
            asm volatile("atom.acq_rel.gpu.global.add.u32 %0, [%1], 1;"
                         : "=r"(ro) : "l"(&g_root) : "memory");
            if (ro == NGRP - 1) {
                asm volatile("st.relaxed.gpu.global.u32 [%0], %1;"
                             :: "l"(&g_root), "r"(0u) : "memory");
                asm volatile("st.release.gpu.global.u32 [%0], %1;"
                             :: "l"(&g_gen), "r"(gen + 1) : "memory");
            } else {
                unsigned cur;
                do {
                    asm volatile("ld.acquire.gpu.global.u32 %0, [%1];"
                                 : "=r"(cur) : "l"(&g_gen) : "memory");
                } while (cur == gen);
            }
        } else {
            unsigned cur;
            do {
                asm volatile("ld.acquire.gpu.global.u32 %0, [%1];"
                             : "=r"(cur) : "l"(&g_gen) : "memory");
            } while (cur == gen);
        }
    }
    __syncthreads();
}

// ---------------------------------------------------------------------------
// Persistent recurrence: 128 blocks x 512 threads; block b owns cols
// [8b, 8b+8) of ALL THREE gates. fp16 m16n8k16 GEMMs, fp32 state.
//   Single-sync 3-stage cp.async ring over NCH=4 chunks of 256 K. (R14 core)
// ---------------------------------------------------------------------------
__global__ void __launch_bounds__(NTHR, 1)
gru_persist(const int* __restrict__ X,
            const float* __restrict__ Wz, const float* __restrict__ bz,
            const float* __restrict__ Wr, const float* __restrict__ br,
            const float* __restrict__ Wh, const float* __restrict__ bh)
{
    extern __shared__ unsigned char smraw[];
    uint32_t* sWa32 = reinterpret_cast<uint32_t*>(smraw);        // 8192 u32 (32KB): z|r frags
    uint32_t* sWh32 = sWa32 + 8192;                              // 4096 u32 (16KB): h frags
    __half*   sAh   = reinterpret_cast<__half*>(sWh32 + 4096);   // 3*64*CHP halves (~99KB)
    float*    sRed  = reinterpret_cast<float*>(sAh + NSTG * 64 * CHP);  // 4608 f
    float*    sZ    = sRed + 2 * 64 * RSTR;                      // 512 f
    float*    sHc   = sZ + 512;                                  // 512 f (own-col H, fp32)

    const int tid  = threadIdx.x;
    const int bid  = blockIdx.x;
    const int lane = tid & 31;
    const int wid  = tid >> 5;
    const int mt   = wid >> 2;
    const int kq   = wid & 3;
    const int gid  = lane >> 2;
    const int tg   = lane & 3;
    const int n0   = bid * 8;
    const int grp  = bid >> 4;      // barrier tree group

    // epilogue thread mapping
    const int erow = tid >> 3;
    const int ecol = tid & 7;
    const int en   = n0 + ecol;

    uint32_t sbase = (uint32_t)__cvta_generic_to_shared(sAh);

    // ---- pack weights once (fp16 b-fragments, RNE) ----
    for (int e = tid; e < 8192; e += NTHR) {
        int c = e & 3, ln = (e >> 2) & 31, k16 = e >> 7;
        int tgp = ln & 3, gidp = ln >> 2;
        int kb  = k16 * 16 + (c & 1) * 8 + 2 * tgp;
        const float* W = (c >> 1) ? Wr : Wz;
        int col = n0 + gidp;
        sWa32[e] = packh2(W[(size_t)(VOCAB + kb) * HID + col],
                          W[(size_t)(VOCAB + kb + 1) * HID + col]);
    }
    for (int e = tid; e < 4096; e += NTHR) {
        int c = e & 1, ln = (e >> 1) & 31, k16 = e >> 6;
        int tgp = ln & 3, gidp = ln >> 2;
        int kb  = k16 * 16 + c * 8 + 2 * tgp;
        int col = n0 + gidp;
        sWh32[e] = packh2(Wh[(size_t)(VOCAB + kb) * HID + col],
                          Wh[(size_t)(VOCAB + kb + 1) * HID + col]);
    }

    // bias preload
    const float bzv = bz[en], brv = br[en], bhv = bh[en];

    // init: H0 = 0 (fp16 operand buffer + own-col fp32 state)
    {
        int idx = bid * NTHR + tid;                 // 65536 = 64*1024
        reinterpret_cast<unsigned short*>(g_Hh)[idx] = 0;
        sHc[tid] = 0.f;
    }
    gridbar(grp);

    for (int t = 0; t < SEQ; ++t) {
        float* Hn = g_H + (size_t)(t + 1) * (BATCH * HID);

        // prefetch gather operands for both epilogues
        const int x = __ldg(X + erow * SEQ + t);
        const size_t wix = (size_t)x * HID + en;
        const float wzv = __ldg(Wz + wix);
        const float wrv = __ldg(Wr + wix);
        const float whv = __ldg(Wh + wix);

        // ================= Phase A: z and r =================
        {
            float az[4] = {0,0,0,0}, ar[4] = {0,0,0,0};

#pragma unroll
            for (int c = 0; c < NSTG; ++c) {
#pragma unroll
                for (int j = 0; j < 4; ++j) {
                    int seg = j * NTHR + tid;
                    int row = seg >> 5, s = seg & 31;
                    uint32_t d = sbase + (c * (64 * CHP) + row * CHP + s * 8) * 2;
                    cpasync16(d, g_Hh + (size_t)row * HID + c * CH + s * 8);
                }
                cpasync_commit();
            }

#pragma unroll
            for (int it = 0; it < NCH; ++it) {
                if (it == 0)           cpasync_wait<NSTG - 1>();
                else if (it + 1 < NCH) cpasync_wait<1>();
                else                   cpasync_wait<0>();
                __syncthreads();

                if (it >= 1 && it + 2 < NCH) {
                    int c = it + 2;
#pragma unroll
                    for (int j = 0; j < 4; ++j) {
                        int seg = j * NTHR + tid;
                        int row = seg >> 5, s = seg & 31;
                        uint32_t d = sbase + ((c % NSTG) * (64 * CHP) + row * CHP + s * 8) * 2;
                        cpasync16(d, g_Hh + (size_t)row * HID + c * CH + s * 8);
                    }
                    cpasync_commit();
                }

                const __half* stg = sAh + (it % NSTG) * (64 * CHP);
                const int row0 = mt * 16 + gid;
#pragma unroll
                for (int i = 0; i < 4; ++i) {
                    int k16l = kq * 4 + i;
                    int kk   = k16l * 16;
                    unsigned u0 = *reinterpret_cast<const unsigned*>(stg + row0 * CHP + kk + 2 * tg);
                    unsigned u1 = *reinterpret_cast<const unsigned*>(stg + (row0 + 8) * CHP + kk + 2 * tg);
                    unsigned u2 = *reinterpret_cast<const unsigned*>(stg + row0 * CHP + kk + 8 + 2 * tg);
                    unsigned u3 = *reinterpret_cast<const unsigned*>(stg + (row0 + 8) * CHP + kk + 8 + 2 * tg);
                    int k16g = it * 16 + k16l;
                    uint4 w = *reinterpret_cast<const uint4*>(sWa32 + (size_t)(k16g * 32 + lane) * 4);
                    mma16(az, u0, u1, u2, u3, w.x, w.y);
                    mma16(ar, u0, u1, u2, u3, w.z, w.w);
                }
            }

            // partials -> sRed[gate][row][col][kq]
#pragma unroll
            for (int j = 0; j < 4; ++j) {
                int prow = mt * 16 + gid + (j >> 1) * 8;
                int pcol = tg * 2 + (j & 1);
                sRed[prow * RSTR + pcol * 4 + kq]             = az[j];
                sRed[64 * RSTR + prow * RSTR + pcol * 4 + kq] = ar[j];
            }
            __syncthreads();

            // wide epilogue: one (row,col) per thread
            {
                float4 zp = *reinterpret_cast<const float4*>(sRed + erow * RSTR + ecol * 4);
                float4 rp = *reinterpret_cast<const float4*>(sRed + 64 * RSTR + erow * RSTR + ecol * 4);
                float zsum = ((zp.x + zp.y) + zp.z) + zp.w;
                float rsum = ((rp.x + rp.y) + rp.z) + rp.w;
                float zv = sigmoidf_(zsum + wzv + bzv);
                float rv = sigmoidf_(rsum + wrv + brv);
                sZ[tid] = zv;
                g_Ph[erow * HID + en] = __float2half_rn(rv * sHc[tid]);
            }
        }
        gridbar(grp);

        // ================= Phase B: h gate + H update =================
        {
            float ah[4] = {0,0,0,0};

#pragma unroll
            for (int c = 0; c < NSTG; ++c) {
#pragma unroll
                for (int j = 0; j < 4; ++j) {
                    int seg = j * NTHR + tid;
                    int row = seg >> 5, s = seg & 31;
                    uint32_t d = sbase + (c * (64 * CHP) + row * CHP + s * 8) * 2;
                    cpasync16(d, g_Ph + (size_t)row * HID + c * CH + s * 8);
                }
                cpasync_commit();
            }

#pragma unroll
            for (int it = 0; it < NCH; ++it) {
                if (it == 0)           cpasync_wait<NSTG - 1>();
                else if (it + 1 < NCH) cpasync_wait<1>();
                else                   cpasync_wait<0>();
                __syncthreads();

                if (it >= 1 && it + 2 < NCH) {
                    int c = it + 2;
#pragma unroll
                    for (int j = 0; j < 4; ++j) {
                        int seg = j * NTHR + tid;
                        int row = seg >> 5, s = seg & 31;
                        uint32_t d = sbase + ((c % NSTG) * (64 * CHP) + row * CHP + s * 8) * 2;
                        cpasync16(d, g_Ph + (size_t)row * HID + c * CH + s * 8);
                    }
                    cpasync_commit();
                }

                const __half* stg = sAh + (it % NSTG) * (64 * CHP);
                const int row0 = mt * 16 + gid;
#pragma unroll
                for (int i = 0; i < 4; ++i) {
                    int k16l = kq * 4 + i;
                    int kk   = k16l * 16;
                    unsigned u0 = *reinterpret_cast<const unsigned*>(stg + row0 * CHP + kk + 2 * tg);
                    unsigned u1 = *reinterpret_cast<const unsigned*>(stg + (row0 + 8) * CHP + kk + 2 * tg);
                    unsigned u2 = *reinterpret_cast<const unsigned*>(stg + row0 * CHP + kk + 8 + 2 * tg);
                    unsigned u3 = *reinterpret_cast<const unsigned*>(stg + (row0 + 8) * CHP + kk + 8 + 2 * tg);
                    int k16g = it * 16 + k16l;
                    uint2 w = *reinterpret_cast<const uint2*>(sWh32 + (size_t)(k16g * 32 + lane) * 2);
                    mma16(ah, u0, u1, u2, u3, w.x, w.y);
                }
            }

#pragma unroll
            for (int j = 0; j < 4; ++j) {
                int prow = mt * 16 + gid + (j >> 1) * 8;
                int pcol = tg * 2 + (j & 1);
                sRed[prow * RSTR + pcol * 4 + kq] = ah[j];
            }
            __syncthreads();

            {
                float4 hp = *reinterpret_cast<const float4*>(sRed + erow * RSTR + ecol * 4);
                float hsum = ((hp.x + hp.y) + hp.z) + hp.w;
                float hv = tanhf(hsum + whv + bhv);
                float zv = sZ[tid];
                float hcold = sHc[tid];
                float hnew = zv * hv + (1.f - zv) * hcold;
                sHc[tid] = hnew;
                Hn[erow * HID + en] = hnew;                       // fp32 history
                g_Hh[erow * HID + en] = __float2half_rn(hnew);    // fp16 operand
            }
        }
        if (t + 1 < SEQ) gridbar(grp);   // final bar unneeded (kernel boundary orders g_H)
    }
}

// ---------------------------------------------------------------------------
// Output GEMM: Y = H_all[16384 x 1024] @ Wo[1024 x 4096] + bo
//   128x128 block tile, 512 threads (known-good, tf32).
// ---------------------------------------------------------------------------
__global__ void __launch_bounds__(512)
gru_out3(const float* __restrict__ Wo, const float* __restrict__ bo,
         float* __restrict__ out)
{
    __shared__ float As[128 * 36];
    __shared__ float Bs[32 * 136];

    const int n0 = blockIdx.x * 128;
    const int m0 = blockIdx.y * 128;
    const float* A = g_H + (size_t)(BATCH * HID) + (size_t)m0 * HID;

    const int tid = threadIdx.x, lane = tid & 31, w = tid >> 5;
    const int wm = w >> 2, wn = w & 3, gid = lane >> 2, tg = lane & 3;

    float acc[2][4][4];
#pragma unroll
    for (int mi = 0; mi < 2; ++mi)
#pragma unroll
        for (int ni = 0; ni < 4; ++ni)
#pragma unroll
            for (int e = 0; e < 4; ++e) acc[mi][ni][e] = 0.f;

    float4 ra[2]; float4 rb[2];
#pragma unroll
    for (int j = 0; j < 2; ++j) {
        int i = tid + j * 512, row = i >> 3, kq8 = i & 7;
        ra[j] = *reinterpret_cast<const float4*>(A + (size_t)row * HID + kq8 * 4);
    }
#pragma unroll
    for (int j = 0; j < 2; ++j) {
        int i = tid + j * 512, row = i >> 5, nq = i & 31;
        rb[j] = *reinterpret_cast<const float4*>(Wo + (size_t)row * VOCAB + n0 + nq * 4);
    }

    for (int kk = 0; kk < HID; kk += 32) {
#pragma unroll
        for (int j = 0; j < 2; ++j) {
            int i = tid + j * 512, row = i >> 3, kq8 = i & 7;
            float4 v; v.x = tf32r(ra[j].x); v.y = tf32r(ra[j].y);
            v.z = tf32r(ra[j].z); v.w = tf32r(ra[j].w);
            *reinterpret_cast<float4*>(As + row * 36 + kq8 * 4) = v;
        }
#pragma unroll
        for (int j = 0; j < 2; ++j) {
            int i = tid + j * 512, row = i >> 5, nq = i & 31;
            float4 v; v.x = tf32r(rb[j].x); v.y = tf32r(rb[j].y);
            v.z = tf32r(rb[j].z); v.w = tf32r(rb[j].w);
            *reinterpret_cast<float4*>(Bs + row * 136 + nq * 4) = v;
        }
        __syncthreads();
        if (kk + 32 < HID) {
#pragma unroll
            for (int j = 0; j < 2; ++j) {
                int i = tid + j * 512, row = i >> 3, kq8 = i & 7;
                ra[j] = *reinterpret_cast<const float4*>(A + (size_t)row * HID + kk + 32 + kq8 * 4);
            }
#pragma unroll
            for (int j = 0; j < 2; ++j) {
                int i = tid + j * 512, row = i >> 5, nq = i & 31;
                rb[j] = *reinterpret_cast<const float4*>(
                    Wo + (size_t)(kk + 32 + row) * VOCAB + n0 + nq * 4);
            }
        }
#pragma unroll
        for (int k8 = 0; k8 < 4; ++k8) {
            int kb = k8 * 8;
            float a[2][4];
#pragma unroll
            for (int mi = 0; mi < 2; ++mi) {
                int rb0 = wm * 32 + mi * 16;
                a[mi][0] = As[(rb0 + gid) * 36 + kb + tg];
                a[mi][1] = As[(rb0 + 8 + gid) * 36 + kb + tg];
                a[mi][2] = As[(rb0 + gid) * 36 + kb + 4 + tg];
                a[mi][3] = As[(rb0 + 8 + gid) * 36 + kb + 4 + tg];
            }
#pragma unroll
            for (int ni = 0; ni < 4; ++ni) {
                int col = wn * 32 + ni * 8 + gid;
                float b0 = Bs[(kb + tg) * 136 + col];
                float b1 = Bs[(kb + 4 + tg) * 136 + col];
#pragma unroll
                for (int mi = 0; mi < 2; ++mi) mma8(acc[mi][ni], a[mi], b0, b1);
            }
        }
        __syncthreads();
    }

#pragma unroll
    for (int mi = 0; mi < 2; ++mi)
#pragma unroll
        for (int half = 0; half < 2; ++half) {
            int row = m0 + wm * 32 + mi * 16 + half * 8 + gid;
#pragma unroll
            for (int ni = 0; ni < 4; ++ni)
#pragma unroll
                for (int e = 0; e < 2; ++e) {
                    int n = n0 + wn * 32 + ni * 8 + tg * 2 + e;
                    out[(size_t)row * VOCAB + n] = acc[mi][ni][half * 2 + e] + bo[n];
                }
        }
}

__global__ void gru_copy_hfinal(float* __restrict__ dst) {
    int i = blockIdx.x * blockDim.x + threadIdx.x;
    if (i < BATCH * HID) dst[i] = g_H[(size_t)SEQ * (BATCH * HID) + i];
}

// ---------------------------------------------------------------------------
extern "C" void kernel_launch(void* const* d_in, const int* in_sizes, int n_in,
                              void* d_out, int out_size)
{
    const int*   X  = (const int*)  d_in[0];
    const float* Wz = (const float*)d_in[1];
    const float* bz = (const float*)d_in[2];
    const float* Wr = (const float*)d_in[3];
    const float* br = (const float*)d_in[4];
    const float* Wh = (const float*)d_in[5];
    const float* bh = (const float*)d_in[6];
    const float* Wo = (const float*)d_in[7];
    const float* bo = (const float*)d_in[8];
    float* out = (float*)d_out;

    const int smemBytes = 8192 * 4            // sWa32
                        + 4096 * 4            // sWh32
                        + NSTG * 64 * CHP * 2 // fp16 A ring
                        + 2 * 64 * RSTR * 4   // sRed
                        + 512 * 4             // sZ
                        + 512 * 4;            // sHc  => 173056 B
    cudaFuncSetAttribute(gru_persist, cudaFuncAttributeMaxDynamicSharedMemorySize, smemBytes);

    gru_persist<<<NBLK, NTHR, smemBytes>>>(X, Wz, bz, Wr, br, Wh, bh);

    gru_out3<<<dim3(VOCAB / 128, (SEQ * BATCH) / 128), 512>>>(Wo, bo, out);

    const long long ybytes = (long long)SEQ * BATCH * VOCAB;
    if ((long long)out_size >= ybytes + (long long)BATCH * HID) {
        gru_copy_hfinal<<<64, 1024>>>(out + ybytes);
    }
    (void)in_sizes; (void)n_in;
}